// round 14
// baseline (speedup 1.0000x reference)
#include <cuda_runtime.h>
#include <cuda_bf16.h>
#include <cstdint>

#define NNODE   16384
#define KNN     9
#define KC      12
#define BCAP    16

typedef unsigned long long u64;
typedef unsigned int u32;

__device__ __align__(256) float g_xf[NNODE * 48];
__device__ float g_sq[NNODE];
__device__ float g_sqB[NNODE];                      // sq with node 16383 -> +INF
__device__ __align__(256) u32 g_packA[NNODE * 48];  // tf32 features (node-major)
__device__ __align__(256) ulonglong2 g_bt[2048 * 96]; // B tiled: [tile][pair][lane]
__device__ float g_pd12[NNODE * 4 * KC];
__device__ int   g_pi12[NNODE * 4 * KC];
__device__ int   g_cand[NNODE * KC];
__device__ int   g_nbr[NNODE * KNN];
__device__ int   g_deg[NNODE];
__device__ float g_dinv[NNODE];

__device__ __forceinline__ u32 to_tf32(float f) {
    u32 r;
    asm("cvt.rna.tf32.f32 %0, %1;" : "=r"(r) : "f"(f));
    return r;
}
__device__ __forceinline__ void cp16(u32 dst_smem, const void* src) {
    asm volatile("cp.async.ca.shared.global [%0], [%1], 16;" :: "r"(dst_smem), "l"(src));
}

// ============ 1: transpose + tf32 pack (A + tiled B) + norms + deg=0 ============
__global__ __launch_bounds__(192) void transpose_kernel(const float* __restrict__ x) {
    int bh = blockIdx.x;
    __shared__ float s[48][65];
    const float* src = x + (size_t)(bh >> 6) * 48 * 4096 + (bh & 63) * 64;
    for (int idx = threadIdx.x; idx < 48 * 64; idx += 192) {
        int c = idx >> 6, w = idx & 63;
        s[c][w] = src[c * 4096 + w];
    }
    __syncthreads();
    float* dst = g_xf + (size_t)bh * 64 * 48;
    for (int idx = threadIdx.x; idx < 48 * 64; idx += 192) {
        int w = idx / 48, c = idx - w * 48;
        dst[w * 48 + c] = s[c][w];
    }
    // pack: thread (w = tid&63, k = tid>>6) handles node bh*64+w, channels 16k..16k+15
    {
        const int w = threadIdx.x & 63, k = threadIdx.x >> 6;
        const int n = bh * 64 + w;
        u32 tv[16];
#pragma unroll
        for (int j = 0; j < 16; j++) tv[j] = to_tf32(s[16 * k + j][w]);
        // A pack (identity layout)
        uint4* pa = (uint4*)(g_packA + (size_t)n * 48 + 16 * k);
#pragma unroll
        for (int q = 0; q < 4; q++)
            pa[q] = make_uint4(tv[4 * q], tv[4 * q + 1], tv[4 * q + 2], tv[4 * q + 3]);
        // B tiled pack: pair p=k holds k-chunks c=2k (tv[0..7]) and c=2k+1 (tv[8..15])
        const int tile = n >> 3, g = n & 7;
        ulonglong2* bt = g_bt + (size_t)tile * 96 + k * 32 + 4 * g;
#pragma unroll
        for (int t = 0; t < 4; t++)
            bt[t] = make_ulonglong2(((u64)tv[t + 4] << 32) | (u64)tv[t],
                                    ((u64)tv[12 + t] << 32) | (u64)tv[8 + t]);
    }
    if (threadIdx.x < 64) {
        int w = threadIdx.x;
        int n = bh * 64 + w;
        float acc = 0.f;
#pragma unroll
        for (int c = 0; c < 48; c++) acc += s[c][w] * s[c][w];
        g_sq[n] = acc;
        g_sqB[n] = (n == NNODE - 1) ? __int_as_float(0x7f800000) : acc;
        g_deg[n] = 0;
    }
}

#define MMA8(C0,C1,C2,C3,A0,A1,A2,A3,B0,B1)                                     \
    asm volatile("mma.sync.aligned.m16n8k8.row.col.f32.tf32.tf32.f32 "          \
        "{%0,%1,%2,%3},{%4,%5,%6,%7},{%8,%9},{%0,%1,%2,%3};"                    \
        : "+f"(C0), "+f"(C1), "+f"(C2), "+f"(C3)                                 \
        : "r"(A0), "r"(A1), "r"(A2), "r"(A3), "r"(B0), "r"(B1))

// exact sorted-insert replay of buffered candidates (FIFO order == ascending j)
// sbuf layout transposed: entry e of thread tid at sbuf[e][tid] (low conflict)
__device__ __forceinline__ void compact_buf(u64 (*sbuf)[132], int tid, int& cnt,
                                            float (&d12)[KC], int (&n12)[KC],
                                            float& dmax) {
    for (int e = 0; e < cnt; e++) {
        u64 v = sbuf[e][tid];
        float dist = __uint_as_float((u32)(v >> 32));
        int idx = (int)(u32)v;
        if (dist < d12[KC - 1]) {
            d12[KC - 1] = dist; n12[KC - 1] = idx;
#pragma unroll
            for (int k = KC - 1; k > 0; k--) {
                if (d12[k] < d12[k - 1]) {
                    float td = d12[k]; d12[k] = d12[k - 1]; d12[k - 1] = td;
                    int   ti = n12[k]; n12[k] = n12[k - 1]; n12[k - 1] = ti;
                }
            }
        }
    }
    cnt = 0;
    dmax = d12[KC - 1];
}

// ============ 2: knn via mma.sync tf32 (K=48) + smem-staged B + lazy top-12 ============
// 512 blocks x 128 thr, 4 blocks/SM. Block = center-group (64 centers) x sweep-half
// (2048 candidates = 256 n8-tiles = 32 chunks of 8 tiles, cp.async double-buffered).
__global__ __launch_bounds__(128, 4) void knn_mma_kernel() {
    __shared__ __align__(16) ulonglong2 sB[2][8][96];  // [buf][tile][pair*32+lane]
    __shared__ float sc[4][16][12];                    // dot scratch per warp
    __shared__ u64 sbuf[BCAP][132];                    // transposed candidate FIFO
    const int tid = threadIdx.x, w = tid >> 5, lane = tid & 31;
    const int g = lane >> 2, t = lane & 3;
    const int grp = blockIdx.x >> 1, H = blockIdx.x & 1;
    const int cb = grp * 64, batch = grp >> 6;
    const int jbq = (batch << 12) + H * 2048;
    const int gt0 = jbq >> 3;                          // first global tile of sweep
    const int r0 = cb + w * 16 + g, r1 = r0 + 8;

    // A fragments for 6 k8-chunks
    u32 a0[6], a1[6], a2[6], a3[6];
    {
        const u32* pa0 = g_packA + (size_t)r0 * 48;
        const u32* pa1 = g_packA + (size_t)r1 * 48;
#pragma unroll
        for (int c = 0; c < 6; c++) {
            a0[c] = pa0[8 * c + t];     a2[c] = pa0[8 * c + t + 4];
            a1[c] = pa1[8 * c + t];     a3[c] = pa1[8 * c + t + 4];
        }
    }
    const int rown = cb + w * 16 + (lane & 15);     // owner center
    const int h = lane >> 4;                        // owner col-half
    const float sqi = g_sq[rown];

    float d12[KC]; int n12[KC];
#pragma unroll
    for (int k = 0; k < KC; k++) { d12[k] = 3.402823466e+38f; n12[k] = 0x7fffffff; }
    float dmax = 3.402823466e+38f;
    int cnt = 0;

    const u32 sB_a[2] = { (u32)__cvta_generic_to_shared(&sB[0][0][0]),
                          (u32)__cvta_generic_to_shared(&sB[1][0][0]) };

    // preload chunk 0 (8 tiles = 768 ulonglong2 = 12KB)
    {
        const ulonglong2* srcp = g_bt + (size_t)gt0 * 96;
#pragma unroll
        for (int q = 0; q < 6; q++)
            cp16(sB_a[0] + (tid + q * 128) * 16, srcp + tid + q * 128);
        asm volatile("cp.async.commit_group;");
    }

#pragma unroll 1
    for (int ch = 0; ch < 32; ch++) {
        const int b = ch & 1;
        __syncthreads();                               // prior chunk fully consumed
        if (ch + 1 < 32) {
            const ulonglong2* srcp = g_bt + (size_t)(gt0 + (ch + 1) * 8) * 96;
#pragma unroll
            for (int q = 0; q < 6; q++)
                cp16(sB_a[b ^ 1] + (tid + q * 128) * 16, srcp + tid + q * 128);
            asm volatile("cp.async.commit_group;");
            asm volatile("cp.async.wait_group 1;" ::: "memory");
        } else {
            asm volatile("cp.async.wait_group 0;" ::: "memory");
        }
        __syncthreads();                               // chunk ch visible

#pragma unroll
        for (int tt = 0; tt < 8; tt++) {
            const int j0 = jbq + (ch * 8 + tt) * 8;
            ulonglong2 q0 = sB[b][tt][lane];
            ulonglong2 q1 = sB[b][tt][32 + lane];
            ulonglong2 q2 = sB[b][tt][64 + lane];
            float cA0 = 0.f, cA1 = 0.f, cA2 = 0.f, cA3 = 0.f;
            float cB0 = 0.f, cB1 = 0.f, cB2 = 0.f, cB3 = 0.f;
            float cC0 = 0.f, cC1 = 0.f, cC2 = 0.f, cC3 = 0.f;
            MMA8(cA0, cA1, cA2, cA3, a0[0], a1[0], a2[0], a3[0], (u32)q0.x, (u32)(q0.x >> 32));
            MMA8(cB0, cB1, cB2, cB3, a0[1], a1[1], a2[1], a3[1], (u32)q0.y, (u32)(q0.y >> 32));
            MMA8(cC0, cC1, cC2, cC3, a0[2], a1[2], a2[2], a3[2], (u32)q1.x, (u32)(q1.x >> 32));
            MMA8(cA0, cA1, cA2, cA3, a0[3], a1[3], a2[3], a3[3], (u32)q1.y, (u32)(q1.y >> 32));
            MMA8(cB0, cB1, cB2, cB3, a0[4], a1[4], a2[4], a3[4], (u32)q2.x, (u32)(q2.x >> 32));
            MMA8(cC0, cC1, cC2, cC3, a0[5], a1[5], a2[5], a3[5], (u32)q2.y, (u32)(q2.y >> 32));
            float c0 = cA0 + cB0 + cC0, c1 = cA1 + cB1 + cC1;
            float c2 = cA2 + cB2 + cC2, c3 = cA3 + cB3 + cC3;
            *reinterpret_cast<float2*>(&sc[w][g][2 * t])     = make_float2(c0, c1);
            *reinterpret_cast<float2*>(&sc[w][g + 8][2 * t]) = make_float2(c2, c3);
            __syncwarp();
            float4 dd = *reinterpret_cast<float4*>(&sc[w][lane & 15][4 * h]);
            float4 sj = *reinterpret_cast<const float4*>(&g_sqB[j0 + 4 * h]);
            const int jc = j0 + 4 * h;
            float dist0 = fmaf(dd.x, -2.0f, sqi + sj.x);
            float dist1 = fmaf(dd.y, -2.0f, sqi + sj.y);
            float dist2 = fmaf(dd.z, -2.0f, sqi + sj.z);
            float dist3 = fmaf(dd.w, -2.0f, sqi + sj.w);
            if (dist0 < dmax) { sbuf[cnt][tid] = ((u64)__float_as_uint(dist0) << 32) | (u32)(jc);     cnt++; }
            if (dist1 < dmax) { sbuf[cnt][tid] = ((u64)__float_as_uint(dist1) << 32) | (u32)(jc + 1); cnt++; }
            if (dist2 < dmax) { sbuf[cnt][tid] = ((u64)__float_as_uint(dist2) << 32) | (u32)(jc + 2); cnt++; }
            if (dist3 < dmax) { sbuf[cnt][tid] = ((u64)__float_as_uint(dist3) << 32) | (u32)(jc + 3); cnt++; }
            if (__any_sync(0xffffffffu, cnt >= BCAP - 4))
                compact_buf(sbuf, tid, cnt, d12, n12, dmax);
            __syncwarp();
        }
    }
    compact_buf(sbuf, tid, cnt, d12, n12, dmax);

    const size_t base = ((size_t)rown * 4 + H * 2 + h) * KC;
#pragma unroll
    for (int k = 0; k < KC; k++) { g_pd12[base + k] = d12[k]; g_pi12[base + k] = n12[k]; }
}

// ============ 3: merge 4 partial lists -> approx top-12 candidates ============
__global__ __launch_bounds__(32) void merge12_kernel() {
    int i = blockIdx.x * 32 + threadIdx.x;
    if (i >= NNODE || i == NNODE - 1) return;       // 16383 handled in rescore
    int p[4] = {0, 0, 0, 0};
#pragma unroll
    for (int k = 0; k < KC; k++) {
        float bd = 3.402823466e+38f; int bi = 0x7fffffff; int bq = 0;
#pragma unroll
        for (int q = 0; q < 4; q++) {
            float dq = g_pd12[((size_t)i * 4 + q) * KC + p[q]];
            int   iq = g_pi12[((size_t)i * 4 + q) * KC + p[q]];
            if (dq < bd || (dq == bd && iq < bi)) { bd = dq; bi = iq; bq = q; }
        }
        p[bq]++;
        g_cand[(size_t)i * KC + k] = bi;
    }
}

// ============ 4: exact rescore of 12 candidates -> top-9 (+ degree atomics) ============
__global__ __launch_bounds__(128) void rescore_kernel() {
    const int wid = threadIdx.x >> 5, lid = threadIdx.x & 31;
    const int i = blockIdx.x * 4 + wid;
    if (i == NNODE - 1) {
        if (lid == 0) {
            g_nbr[i * KNN + 0] = NNODE - 1;
            atomicAdd(&g_deg[NNODE - 1], 1);
#pragma unroll
            for (int k = 1; k < KNN; k++) {
                g_nbr[i * KNN + k] = k - 1;
                atomicAdd(&g_deg[k - 1], 1);
            }
        }
        return;
    }
    int cj = g_cand[(size_t)i * KC + (lid < KC ? lid : 0)];
    float dist = 3.402823466e+38f;
    if (lid < KC) {
        const float4* xa = (const float4*)(g_xf + (size_t)i * 48);
        const float4* xb = (const float4*)(g_xf + (size_t)cj * 48);
        float dot = 0.f;
#pragma unroll
        for (int k = 0; k < 12; k++) {
            float4 a = xa[k], b = xb[k];
            dot += a.x * b.x + a.y * b.y + a.z * b.z + a.w * b.w;
        }
        dist = g_sq[i] + g_sq[cj] - 2.0f * dot;
    }
    float dd[KC]; int nn[KC];
#pragma unroll
    for (int q = 0; q < KC; q++) {
        dd[q] = __shfl_sync(0xffffffff, dist, q);
        nn[q] = __shfl_sync(0xffffffff, cj, q);
    }
    if (lid == 0) {
#pragma unroll
        for (int k = 0; k < KNN; k++) {
            float bd = 3.402823466e+38f; int bi = 0x7fffffff; int bq = 0;
#pragma unroll
            for (int q = 0; q < KC; q++) {
                if (dd[q] < bd || (dd[q] == bd && nn[q] < bi)) { bd = dd[q]; bi = nn[q]; bq = q; }
            }
            dd[bq] = 3.402823466e+38f;
            g_nbr[i * KNN + k] = bi;
            atomicAdd(&g_deg[bi], 1);
        }
    }
}

// ============ 5: dinv ============
__global__ __launch_bounds__(256) void dinv_kernel() {
    int i = blockIdx.x * 256 + threadIdx.x;
    if (i < NNODE) g_dinv[i] = rsqrtf((float)g_deg[i]);
}

// ============ 6: fused gather + (xf@W0 + tx1@W1 + b) + relu ============
__global__ __launch_bounds__(384) void out_kernel(const float* __restrict__ W0,
                                                  const float* __restrict__ W1,
                                                  const float* __restrict__ b,
                                                  float* __restrict__ out) {
    __shared__ float W0s[2304], W1s[2304], bs[48];
    __shared__ float sx[8][48], sg[8][48], sdin[8];
    const int tid = threadIdx.x;
    for (int k = tid; k < 2304; k += 384) { W0s[k] = W0[k]; W1s[k] = W1[k]; }
    if (tid < 48) bs[tid] = b[tid];

    const int row = tid / 48, o = tid % 48;
    const int i = blockIdx.x * 8 + row;

    sx[row][o] = g_xf[(size_t)i * 48 + o];
    float g = 0.f;
    const int* nb = &g_nbr[i * KNN];
#pragma unroll
    for (int k = 0; k < KNN; k++) {
        const int j = nb[k];
        g += g_dinv[j] * g_xf[(size_t)j * 48 + o];
    }
    sg[row][o] = g;
    if (o == 0) sdin[row] = g_dinv[i];
    __syncthreads();

    float a0 = 0.f, a1 = 0.f;
#pragma unroll
    for (int c = 0; c < 48; c++) {
        a0 += sx[row][c] * W0s[c * 48 + o];
        a1 += sg[row][c] * W1s[c * 48 + o];
    }
    const float v = bs[o] + a0 - sdin[row] * a1;
    out[(size_t)i * 48 + o] = fmaxf(v, 0.f);
}

// ============ launch ============
extern "C" void kernel_launch(void* const* d_in, const int* in_sizes, int n_in,
                              void* d_out, int out_size) {
    const float* x  = (const float*)d_in[0];
    const float* W0 = (const float*)d_in[1];
    const float* W1 = (const float*)d_in[2];
    const float* b  = (const float*)d_in[3];
    float* out = (float*)d_out;

    transpose_kernel<<<256, 192>>>(x);
    knn_mma_kernel<<<512, 128>>>();
    merge12_kernel<<<NNODE / 32, 32>>>();
    rescore_kernel<<<NNODE / 4, 128>>>();
    dinv_kernel<<<NNODE / 256, 256>>>();
    out_kernel<<<NNODE / 8, 384>>>(W0, W1, b, out);
}

// round 15
// speedup vs baseline: 1.1079x; 1.1079x over previous
#include <cuda_runtime.h>
#include <cuda_bf16.h>
#include <cstdint>

#define NNODE   16384
#define KNN     9
#define KC      12
#define BCAP    16

typedef unsigned long long u64;
typedef unsigned int u32;

__device__ __align__(256) float g_xf[NNODE * 48];
__device__ float g_sq[NNODE];
__device__ float g_sqB[NNODE];                      // sq with node 16383 -> +INF
__device__ __align__(256) u32 g_packA[NNODE * 48];  // tf32 features
__device__ __align__(256) u64 g_packB2[NNODE * 24]; // fragment-ordered tf32 u64 (b0,b1)
__device__ float g_pd12[NNODE * 4 * KC];
__device__ int   g_pi12[NNODE * 4 * KC];
__device__ int   g_cand[NNODE * KC];
__device__ int   g_nbr[NNODE * KNN];
__device__ int   g_deg[NNODE];
__device__ float g_dinv[NNODE];

__device__ __forceinline__ u32 to_tf32(float f) {
    u32 r;
    asm("cvt.rna.tf32.f32 %0, %1;" : "=r"(r) : "f"(f));
    return r;
}

// ============ 1: transpose + norms + deg=0 ============
__global__ __launch_bounds__(192) void transpose_kernel(const float* __restrict__ x) {
    int bh = blockIdx.x;
    __shared__ float s[48][65];
    const float* src = x + (size_t)(bh >> 6) * 48 * 4096 + (bh & 63) * 64;
    for (int idx = threadIdx.x; idx < 48 * 64; idx += 192) {
        int c = idx >> 6, w = idx & 63;
        s[c][w] = src[c * 4096 + w];
    }
    __syncthreads();
    float* dst = g_xf + (size_t)bh * 64 * 48;
    for (int idx = threadIdx.x; idx < 48 * 64; idx += 192) {
        int w = idx / 48, c = idx - w * 48;
        dst[w * 48 + c] = s[c][w];
    }
    if (threadIdx.x < 64) {
        int w = threadIdx.x;
        float acc = 0.f;
#pragma unroll
        for (int c = 0; c < 48; c++) acc += s[c][w] * s[c][w];
        g_sq[bh * 64 + w] = acc;
        g_deg[bh * 64 + w] = 0;
    }
}

// ============ 2: pack tf32 ============
__global__ __launch_bounds__(256) void pack_kernel() {
    int n = blockIdx.x * 256 + threadIdx.x;
    const float* xr = g_xf + (size_t)n * 48;
    u32 tv[48];
#pragma unroll
    for (int c = 0; c < 48; c++) tv[c] = to_tf32(xr[c]);
    u32* A = g_packA + (size_t)n * 48;
#pragma unroll
    for (int c = 0; c < 48; c++) A[c] = tv[c];
    u64* B2 = g_packB2 + (size_t)n * 24;
#pragma unroll
    for (int c = 0; c < 6; c++)
#pragma unroll
        for (int t = 0; t < 4; t++)
            B2[c * 4 + t] = ((u64)tv[8 * c + t + 4] << 32) | (u64)tv[8 * c + t];
    g_sqB[n] = (n == NNODE - 1) ? __int_as_float(0x7f800000) : g_sq[n];
}

#define MMA8(C0,C1,C2,C3,A0,A1,A2,A3,B0,B1)                                     \
    asm volatile("mma.sync.aligned.m16n8k8.row.col.f32.tf32.tf32.f32 "          \
        "{%0,%1,%2,%3},{%4,%5,%6,%7},{%8,%9},{%0,%1,%2,%3};"                    \
        : "+f"(C0), "+f"(C1), "+f"(C2), "+f"(C3)                                 \
        : "r"(A0), "r"(A1), "r"(A2), "r"(A3), "r"(B0), "r"(B1))

// exact sorted-insert replay of buffered candidates (FIFO order == ascending j)
// sbuf transposed: entry e of thread tid at sbuf[e][tid] -> conflict-free
__device__ __forceinline__ void compact_buf(u64 (*sbuf)[132], int tid, int& cnt,
                                            float (&d12)[KC], int (&n12)[KC],
                                            float& dmax) {
    for (int e = 0; e < cnt; e++) {
        u64 v = sbuf[e][tid];
        float dist = __uint_as_float((u32)(v >> 32));
        int idx = (int)(u32)v;
        if (dist < d12[KC - 1]) {
            d12[KC - 1] = dist; n12[KC - 1] = idx;
#pragma unroll
            for (int k = KC - 1; k > 0; k--) {
                if (d12[k] < d12[k - 1]) {
                    float td = d12[k]; d12[k] = d12[k - 1]; d12[k - 1] = td;
                    int   ti = n12[k]; n12[k] = n12[k - 1]; n12[k - 1] = ti;
                }
            }
        }
    }
    cnt = 0;
    dmax = d12[KC - 1];
}

// ============ 3: knn via mma.sync tf32 (K=48) + lazy top-12 ============
// 512 blocks x 128 thr, 4 blocks/SM. Block = center-group (64 centers) x sweep-half.
__global__ __launch_bounds__(128, 4) void knn_mma_kernel() {
    __shared__ float sc[4][16][12];                 // padded dot scratch per warp
    __shared__ u64 sbuf[BCAP][132];                 // transposed candidate FIFO
    const int tid = threadIdx.x, w = tid >> 5, lane = tid & 31;
    const int g = lane >> 2, t = lane & 3;
    const int grp = blockIdx.x >> 1, H = blockIdx.x & 1;
    const int cb = grp * 64, batch = grp >> 6;
    const int jbq = (batch << 12) + H * 2048;
    const int r0 = cb + w * 16 + g, r1 = r0 + 8;

    // A fragments for 6 k8-chunks
    u32 a0[6], a1[6], a2[6], a3[6];
    {
        const u32* pa0 = g_packA + (size_t)r0 * 48;
        const u32* pa1 = g_packA + (size_t)r1 * 48;
#pragma unroll
        for (int c = 0; c < 6; c++) {
            a0[c] = pa0[8 * c + t];     a2[c] = pa0[8 * c + t + 4];
            a1[c] = pa1[8 * c + t];     a3[c] = pa1[8 * c + t + 4];
        }
    }
    const int rown = cb + w * 16 + (lane & 15);     // owner center
    const int h = lane >> 4;                        // owner col-half
    const float sqi = g_sq[rown];

    float d12[KC]; int n12[KC];
#pragma unroll
    for (int k = 0; k < KC; k++) { d12[k] = 3.402823466e+38f; n12[k] = 0x7fffffff; }
    float dmax = 3.402823466e+38f;
    int cnt = 0;

    const u64* pb = g_packB2 + ((size_t)jbq + g) * 24;
    u64 bc[6];
#pragma unroll
    for (int c = 0; c < 6; c++) bc[c] = pb[c * 4 + t];
    pb += 192;                                      // 8 nodes * 24 u64

#pragma unroll 1
    for (int tile = 0; tile < 256; tile++) {
        u64 bn[6];
        if (tile + 1 < 256) {
#pragma unroll
            for (int c = 0; c < 6; c++) bn[c] = pb[c * 4 + t];
            pb += 192;
        }
        const int j0 = jbq + tile * 8;
        float cA0 = 0.f, cA1 = 0.f, cA2 = 0.f, cA3 = 0.f;
        float cB0 = 0.f, cB1 = 0.f, cB2 = 0.f, cB3 = 0.f;
        float cC0 = 0.f, cC1 = 0.f, cC2 = 0.f, cC3 = 0.f;
#pragma unroll
        for (int c = 0; c < 6; c++) {
            u32 b0 = (u32)bc[c], b1 = (u32)(bc[c] >> 32);
            if (c % 3 == 0)      MMA8(cA0, cA1, cA2, cA3, a0[c], a1[c], a2[c], a3[c], b0, b1);
            else if (c % 3 == 1) MMA8(cB0, cB1, cB2, cB3, a0[c], a1[c], a2[c], a3[c], b0, b1);
            else                 MMA8(cC0, cC1, cC2, cC3, a0[c], a1[c], a2[c], a3[c], b0, b1);
        }
        float c0 = cA0 + cB0 + cC0, c1 = cA1 + cB1 + cC1;
        float c2 = cA2 + cB2 + cC2, c3 = cA3 + cB3 + cC3;
        *reinterpret_cast<float2*>(&sc[w][g][2 * t])     = make_float2(c0, c1);
        *reinterpret_cast<float2*>(&sc[w][g + 8][2 * t]) = make_float2(c2, c3);
        __syncwarp();
        float4 dd = *reinterpret_cast<float4*>(&sc[w][lane & 15][4 * h]);
        float4 sj = *reinterpret_cast<const float4*>(&g_sqB[j0 + 4 * h]);
        const int jc = j0 + 4 * h;
        float dist0 = fmaf(dd.x, -2.0f, sqi + sj.x);
        float dist1 = fmaf(dd.y, -2.0f, sqi + sj.y);
        float dist2 = fmaf(dd.z, -2.0f, sqi + sj.z);
        float dist3 = fmaf(dd.w, -2.0f, sqi + sj.w);
        if (dist0 < dmax) { sbuf[cnt][tid] = ((u64)__float_as_uint(dist0) << 32) | (u32)(jc);     cnt++; }
        if (dist1 < dmax) { sbuf[cnt][tid] = ((u64)__float_as_uint(dist1) << 32) | (u32)(jc + 1); cnt++; }
        if (dist2 < dmax) { sbuf[cnt][tid] = ((u64)__float_as_uint(dist2) << 32) | (u32)(jc + 2); cnt++; }
        if (dist3 < dmax) { sbuf[cnt][tid] = ((u64)__float_as_uint(dist3) << 32) | (u32)(jc + 3); cnt++; }
        if (__any_sync(0xffffffffu, cnt >= BCAP - 4))
            compact_buf(sbuf, tid, cnt, d12, n12, dmax);
        __syncwarp();
#pragma unroll
        for (int c = 0; c < 6; c++) bc[c] = bn[c];
    }
    compact_buf(sbuf, tid, cnt, d12, n12, dmax);

    const size_t base = ((size_t)rown * 4 + H * 2 + h) * KC;
#pragma unroll
    for (int k = 0; k < KC; k++) { g_pd12[base + k] = d12[k]; g_pi12[base + k] = n12[k]; }
}

// ============ 4: merge 4 partial lists -> approx top-12 candidates ============
__global__ __launch_bounds__(128) void merge12_kernel() {
    int i = blockIdx.x * 128 + threadIdx.x;
    if (i >= NNODE || i == NNODE - 1) return;       // 16383 handled in rescore
    int p[4] = {0, 0, 0, 0};
#pragma unroll
    for (int k = 0; k < KC; k++) {
        float bd = 3.402823466e+38f; int bi = 0x7fffffff; int bq = 0;
#pragma unroll
        for (int q = 0; q < 4; q++) {
            float dq = g_pd12[((size_t)i * 4 + q) * KC + p[q]];
            int   iq = g_pi12[((size_t)i * 4 + q) * KC + p[q]];
            if (dq < bd || (dq == bd && iq < bi)) { bd = dq; bi = iq; bq = q; }
        }
        p[bq]++;
        g_cand[(size_t)i * KC + k] = bi;
    }
}

// ============ 5: exact rescore of 12 candidates -> top-9 (+ degree atomics) ============
// warp butterfly min-reduce on (dist, idx), exact lex tie-break, invalidate by idx
__global__ __launch_bounds__(128) void rescore_kernel() {
    const int wid = threadIdx.x >> 5, lid = threadIdx.x & 31;
    const int i = blockIdx.x * 4 + wid;
    if (i == NNODE - 1) {
        if (lid == 0) {
            g_nbr[i * KNN + 0] = NNODE - 1;
            atomicAdd(&g_deg[NNODE - 1], 1);
#pragma unroll
            for (int k = 1; k < KNN; k++) {
                g_nbr[i * KNN + k] = k - 1;
                atomicAdd(&g_deg[k - 1], 1);
            }
        }
        return;
    }
    int cj = g_cand[(size_t)i * KC + (lid < KC ? lid : 0)];
    float dist = 3.402823466e+38f;
    if (lid < KC) {
        const float4* xa = (const float4*)(g_xf + (size_t)i * 48);
        const float4* xb = (const float4*)(g_xf + (size_t)cj * 48);
        float dot = 0.f;
#pragma unroll
        for (int k = 0; k < 12; k++) {
            float4 a = xa[k], b = xb[k];
            dot += a.x * b.x + a.y * b.y + a.z * b.z + a.w * b.w;
        }
        dist = g_sq[i] + g_sq[cj] - 2.0f * dot;
    } else {
        cj = 0x7fffffff;
    }
#pragma unroll
    for (int k = 0; k < KNN; k++) {
        float md = dist; int mi = cj;
#pragma unroll
        for (int off = 16; off >= 1; off >>= 1) {
            float od = __shfl_xor_sync(0xffffffffu, md, off);
            int   oi = __shfl_xor_sync(0xffffffffu, mi, off);
            if (od < md || (od == md && oi < mi)) { md = od; mi = oi; }
        }
        if (lid == 0) {
            g_nbr[i * KNN + k] = mi;
            atomicAdd(&g_deg[mi], 1);
        }
        if (cj == mi) dist = 3.402823466e+38f;   // idx unique -> exact invalidation
    }
}

// ============ 6: dinv ============
__global__ __launch_bounds__(256) void dinv_kernel() {
    int i = blockIdx.x * 256 + threadIdx.x;
    if (i < NNODE) g_dinv[i] = rsqrtf((float)g_deg[i]);
}

// ============ 7: fused gather + (xf@W0 + tx1@W1 + b) + relu ============
__global__ __launch_bounds__(384) void out_kernel(const float* __restrict__ W0,
                                                  const float* __restrict__ W1,
                                                  const float* __restrict__ b,
                                                  float* __restrict__ out) {
    __shared__ float W0s[2304], W1s[2304], bs[48];
    __shared__ float sx[8][48], sg[8][48], sdin[8];
    const int tid = threadIdx.x;
    for (int k = tid; k < 2304; k += 384) { W0s[k] = W0[k]; W1s[k] = W1[k]; }
    if (tid < 48) bs[tid] = b[tid];

    const int row = tid / 48, o = tid % 48;
    const int i = blockIdx.x * 8 + row;

    sx[row][o] = g_xf[(size_t)i * 48 + o];
    float g = 0.f;
    const int* nb = &g_nbr[i * KNN];
#pragma unroll
    for (int k = 0; k < KNN; k++) {
        const int j = nb[k];
        g += g_dinv[j] * g_xf[(size_t)j * 48 + o];
    }
    sg[row][o] = g;
    if (o == 0) sdin[row] = g_dinv[i];
    __syncthreads();

    float a0 = 0.f, a1 = 0.f;
#pragma unroll
    for (int c = 0; c < 48; c++) {
        a0 += sx[row][c] * W0s[c * 48 + o];
        a1 += sg[row][c] * W1s[c * 48 + o];
    }
    const float v = bs[o] + a0 - sdin[row] * a1;
    out[(size_t)i * 48 + o] = fmaxf(v, 0.f);
}

// ============ launch ============
extern "C" void kernel_launch(void* const* d_in, const int* in_sizes, int n_in,
                              void* d_out, int out_size) {
    const float* x  = (const float*)d_in[0];
    const float* W0 = (const float*)d_in[1];
    const float* W1 = (const float*)d_in[2];
    const float* b  = (const float*)d_in[3];
    float* out = (float*)d_out;

    transpose_kernel<<<256, 192>>>(x);
    pack_kernel<<<NNODE / 256, 256>>>();
    knn_mma_kernel<<<512, 128>>>();
    merge12_kernel<<<NNODE / 128, 128>>>();
    rescore_kernel<<<NNODE / 4, 128>>>();
    dinv_kernel<<<NNODE / 256, 256>>>();
    out_kernel<<<NNODE / 8, 384>>>(W0, W1, b, out);
}

// round 16
// speedup vs baseline: 1.6410x; 1.4813x over previous
#include <cuda_runtime.h>
#include <cuda_bf16.h>
#include <cstdint>

#define NNODE   16384
#define KNN     9
#define KC      12
#define BCAP    16

typedef unsigned long long u64;
typedef unsigned int u32;

__device__ __align__(256) float g_xf[NNODE * 48];
__device__ float g_sq[NNODE];
__device__ float g_sqB[NNODE];                      // sq with node 16383 -> +INF
__device__ __align__(256) u32 g_packA[NNODE * 48];  // tf32 features
__device__ __align__(256) u64 g_packB2[NNODE * 24]; // fragment-ordered tf32 u64 (b0,b1)
__device__ float g_pd12[NNODE * 4 * KC];
__device__ int   g_pi12[NNODE * 4 * KC];
__device__ int   g_cand[NNODE * KC];
__device__ int   g_nbr[NNODE * KNN];
__device__ int   g_deg[NNODE];
__device__ float g_dinv[NNODE];

__device__ __forceinline__ u32 to_tf32(float f) {
    u32 r;
    asm("cvt.rna.tf32.f32 %0, %1;" : "=r"(r) : "f"(f));
    return r;
}

// ============ 1: transpose + norms + deg=0 ============
__global__ __launch_bounds__(192) void transpose_kernel(const float* __restrict__ x) {
    int bh = blockIdx.x;
    __shared__ float s[48][65];
    const float* src = x + (size_t)(bh >> 6) * 48 * 4096 + (bh & 63) * 64;
    for (int idx = threadIdx.x; idx < 48 * 64; idx += 192) {
        int c = idx >> 6, w = idx & 63;
        s[c][w] = src[c * 4096 + w];
    }
    __syncthreads();
    float* dst = g_xf + (size_t)bh * 64 * 48;
    for (int idx = threadIdx.x; idx < 48 * 64; idx += 192) {
        int w = idx / 48, c = idx - w * 48;
        dst[w * 48 + c] = s[c][w];
    }
    if (threadIdx.x < 64) {
        int w = threadIdx.x;
        float acc = 0.f;
#pragma unroll
        for (int c = 0; c < 48; c++) acc += s[c][w] * s[c][w];
        g_sq[bh * 64 + w] = acc;
        g_deg[bh * 64 + w] = 0;
    }
}

// ============ 2: pack tf32 ============
__global__ __launch_bounds__(256) void pack_kernel() {
    int n = blockIdx.x * 256 + threadIdx.x;
    const float* xr = g_xf + (size_t)n * 48;
    u32 tv[48];
#pragma unroll
    for (int c = 0; c < 48; c++) tv[c] = to_tf32(xr[c]);
    u32* A = g_packA + (size_t)n * 48;
#pragma unroll
    for (int c = 0; c < 48; c++) A[c] = tv[c];
    u64* B2 = g_packB2 + (size_t)n * 24;
#pragma unroll
    for (int c = 0; c < 6; c++)
#pragma unroll
        for (int t = 0; t < 4; t++)
            B2[c * 4 + t] = ((u64)tv[8 * c + t + 4] << 32) | (u64)tv[8 * c + t];
    g_sqB[n] = (n == NNODE - 1) ? __int_as_float(0x7f800000) : g_sq[n];
}

#define MMA8(C0,C1,C2,C3,A0,A1,A2,A3,B0,B1)                                     \
    asm volatile("mma.sync.aligned.m16n8k8.row.col.f32.tf32.tf32.f32 "          \
        "{%0,%1,%2,%3},{%4,%5,%6,%7},{%8,%9},{%0,%1,%2,%3};"                    \
        : "+f"(C0), "+f"(C1), "+f"(C2), "+f"(C3)                                 \
        : "r"(A0), "r"(A1), "r"(A2), "r"(A3), "r"(B0), "r"(B1))

// exact sorted-insert replay of buffered candidates (FIFO order == ascending j)
__device__ __forceinline__ void compact_buf(u64* buf, int& cnt,
                                            float (&d12)[KC], int (&n12)[KC],
                                            float& dmax) {
    for (int e = 0; e < cnt; e++) {
        u64 v = buf[e];
        float dist = __uint_as_float((u32)(v >> 32));
        int idx = (int)(u32)v;
        if (dist < d12[KC - 1]) {
            d12[KC - 1] = dist; n12[KC - 1] = idx;
#pragma unroll
            for (int k = KC - 1; k > 0; k--) {
                if (d12[k] < d12[k - 1]) {
                    float td = d12[k]; d12[k] = d12[k - 1]; d12[k - 1] = td;
                    int   ti = n12[k]; n12[k] = n12[k - 1]; n12[k - 1] = ti;
                }
            }
        }
    }
    cnt = 0;
    dmax = d12[KC - 1];
}

// ============ 3: knn via mma.sync tf32 (K=48) + lazy top-12 ============
// 512 blocks x 128 thr, 4 blocks/SM. Block = center-group (64 centers) x sweep-half.
__global__ __launch_bounds__(128, 4) void knn_mma_kernel() {
    __shared__ float sc[2][4][16][12];              // double-buffered dot scratch
    __shared__ u64 sbuf[128][BCAP];                 // per-lane candidate FIFO
    const int tid = threadIdx.x, w = tid >> 5, lane = tid & 31;
    const int g = lane >> 2, t = lane & 3;
    const int grp = blockIdx.x >> 1, H = blockIdx.x & 1;
    const int cb = grp * 64, batch = grp >> 6;
    const int jbq = (batch << 12) + H * 2048;
    const int r0 = cb + w * 16 + g, r1 = r0 + 8;

    // A fragments for 6 k8-chunks
    u32 a0[6], a1[6], a2[6], a3[6];
    {
        const u32* pa0 = g_packA + (size_t)r0 * 48;
        const u32* pa1 = g_packA + (size_t)r1 * 48;
#pragma unroll
        for (int c = 0; c < 6; c++) {
            a0[c] = pa0[8 * c + t];     a2[c] = pa0[8 * c + t + 4];
            a1[c] = pa1[8 * c + t];     a3[c] = pa1[8 * c + t + 4];
        }
    }
    const int rown = cb + w * 16 + (lane & 15);     // owner center
    const int h = lane >> 4;                        // owner col-half
    const float sqi = g_sq[rown];

    float d12[KC]; int n12[KC];
#pragma unroll
    for (int k = 0; k < KC; k++) { d12[k] = 3.402823466e+38f; n12[k] = 0x7fffffff; }
    float dmax = 3.402823466e+38f;
    int cnt = 0;
    u64* mybuf = &sbuf[tid][0];

    const u64* pb = g_packB2 + ((size_t)jbq + g) * 24;
    u64 bc[6];
#pragma unroll
    for (int c = 0; c < 6; c++) bc[c] = pb[c * 4 + t];
    pb += 192;                                      // 8 nodes * 24 u64

#pragma unroll 2
    for (int tile = 0; tile < 256; tile++) {
        u64 bn[6];
        if (tile + 1 < 256) {
#pragma unroll
            for (int c = 0; c < 6; c++) bn[c] = pb[c * 4 + t];
            pb += 192;
        }
        const int buf = tile & 1;
        const int j0 = jbq + tile * 8;
        float cA0 = 0.f, cA1 = 0.f, cA2 = 0.f, cA3 = 0.f;
        float cB0 = 0.f, cB1 = 0.f, cB2 = 0.f, cB3 = 0.f;
        float cC0 = 0.f, cC1 = 0.f, cC2 = 0.f, cC3 = 0.f;
#pragma unroll
        for (int c = 0; c < 6; c++) {
            u32 b0 = (u32)bc[c], b1 = (u32)(bc[c] >> 32);
            if (c % 3 == 0)      MMA8(cA0, cA1, cA2, cA3, a0[c], a1[c], a2[c], a3[c], b0, b1);
            else if (c % 3 == 1) MMA8(cB0, cB1, cB2, cB3, a0[c], a1[c], a2[c], a3[c], b0, b1);
            else                 MMA8(cC0, cC1, cC2, cC3, a0[c], a1[c], a2[c], a3[c], b0, b1);
        }
        float c0 = cA0 + cB0 + cC0, c1 = cA1 + cB1 + cC1;
        float c2 = cA2 + cB2 + cC2, c3 = cA3 + cB3 + cC3;
        *reinterpret_cast<float2*>(&sc[buf][w][g][2 * t])     = make_float2(c0, c1);
        *reinterpret_cast<float2*>(&sc[buf][w][g + 8][2 * t]) = make_float2(c2, c3);
        __syncwarp();
        float4 dd = *reinterpret_cast<float4*>(&sc[buf][w][lane & 15][4 * h]);
        float4 sj = *reinterpret_cast<const float4*>(&g_sqB[j0 + 4 * h]);
        const int jc = j0 + 4 * h;
        float dist0 = fmaf(dd.x, -2.0f, sqi + sj.x);
        float dist1 = fmaf(dd.y, -2.0f, sqi + sj.y);
        float dist2 = fmaf(dd.z, -2.0f, sqi + sj.z);
        float dist3 = fmaf(dd.w, -2.0f, sqi + sj.w);
        if (dist0 < dmax) { mybuf[cnt] = ((u64)__float_as_uint(dist0) << 32) | (u32)(jc);     cnt++; }
        if (dist1 < dmax) { mybuf[cnt] = ((u64)__float_as_uint(dist1) << 32) | (u32)(jc + 1); cnt++; }
        if (dist2 < dmax) { mybuf[cnt] = ((u64)__float_as_uint(dist2) << 32) | (u32)(jc + 2); cnt++; }
        if (dist3 < dmax) { mybuf[cnt] = ((u64)__float_as_uint(dist3) << 32) | (u32)(jc + 3); cnt++; }
        if (__any_sync(0xffffffffu, cnt >= BCAP - 4))
            compact_buf(mybuf, cnt, d12, n12, dmax);
        // no trailing syncwarp: sc is double-buffered; the full-mask __any_sync
        // of tiles t and t+1 orders all lanes' reads(t) before writes(t+2)
#pragma unroll
        for (int c = 0; c < 6; c++) bc[c] = bn[c];
    }
    compact_buf(mybuf, cnt, d12, n12, dmax);

    const size_t base = ((size_t)rown * 4 + H * 2 + h) * KC;
#pragma unroll
    for (int k = 0; k < KC; k++) { g_pd12[base + k] = d12[k]; g_pi12[base + k] = n12[k]; }
}

// ============ 4: merge 4 partial lists -> approx top-12 candidates ============
__global__ __launch_bounds__(256) void merge12_kernel() {
    int i = blockIdx.x * 256 + threadIdx.x;
    if (i >= NNODE || i == NNODE - 1) return;       // 16383 handled in rescore
    int p[4] = {0, 0, 0, 0};
#pragma unroll
    for (int k = 0; k < KC; k++) {
        float bd = 3.402823466e+38f; int bi = 0x7fffffff; int bq = 0;
#pragma unroll
        for (int q = 0; q < 4; q++) {
            float dq = g_pd12[((size_t)i * 4 + q) * KC + p[q]];
            int   iq = g_pi12[((size_t)i * 4 + q) * KC + p[q]];
            if (dq < bd || (dq == bd && iq < bi)) { bd = dq; bi = iq; bq = q; }
        }
        p[bq]++;
        g_cand[(size_t)i * KC + k] = bi;
    }
}

// ============ 5: exact rescore of 12 candidates -> top-9 (+ degree atomics) ============
__global__ __launch_bounds__(128) void rescore_kernel() {
    const int wid = threadIdx.x >> 5, lid = threadIdx.x & 31;
    const int i = blockIdx.x * 4 + wid;
    if (i == NNODE - 1) {
        if (lid == 0) {
            g_nbr[i * KNN + 0] = NNODE - 1;
            atomicAdd(&g_deg[NNODE - 1], 1);
#pragma unroll
            for (int k = 1; k < KNN; k++) {
                g_nbr[i * KNN + k] = k - 1;
                atomicAdd(&g_deg[k - 1], 1);
            }
        }
        return;
    }
    int cj = g_cand[(size_t)i * KC + (lid < KC ? lid : 0)];
    float dist = 3.402823466e+38f;
    if (lid < KC) {
        const float4* xa = (const float4*)(g_xf + (size_t)i * 48);
        const float4* xb = (const float4*)(g_xf + (size_t)cj * 48);
        float dot = 0.f;
#pragma unroll
        for (int k = 0; k < 12; k++) {
            float4 a = xa[k], b = xb[k];
            dot += a.x * b.x + a.y * b.y + a.z * b.z + a.w * b.w;
        }
        dist = g_sq[i] + g_sq[cj] - 2.0f * dot;
    }
    float dd[KC]; int nn[KC];
#pragma unroll
    for (int q = 0; q < KC; q++) {
        dd[q] = __shfl_sync(0xffffffff, dist, q);
        nn[q] = __shfl_sync(0xffffffff, cj, q);
    }
    if (lid == 0) {
#pragma unroll
        for (int k = 0; k < KNN; k++) {
            float bd = 3.402823466e+38f; int bi = 0x7fffffff; int bq = 0;
#pragma unroll
            for (int q = 0; q < KC; q++) {
                if (dd[q] < bd || (dd[q] == bd && nn[q] < bi)) { bd = dd[q]; bi = nn[q]; bq = q; }
            }
            dd[bq] = 3.402823466e+38f;
            g_nbr[i * KNN + k] = bi;
            atomicAdd(&g_deg[bi], 1);
        }
    }
}

// ============ 6: dinv ============
__global__ __launch_bounds__(256) void dinv_kernel() {
    int i = blockIdx.x * 256 + threadIdx.x;
    if (i < NNODE) g_dinv[i] = rsqrtf((float)g_deg[i]);
}

// ============ 7: fused gather + (xf@W0 + tx1@W1 + b) + relu ============
__global__ __launch_bounds__(384) void out_kernel(const float* __restrict__ W0,
                                                  const float* __restrict__ W1,
                                                  const float* __restrict__ b,
                                                  float* __restrict__ out) {
    __shared__ float W0s[2304], W1s[2304], bs[48];
    __shared__ float sx[8][48], sg[8][48], sdin[8];
    const int tid = threadIdx.x;
    for (int k = tid; k < 2304; k += 384) { W0s[k] = W0[k]; W1s[k] = W1[k]; }
    if (tid < 48) bs[tid] = b[tid];

    const int row = tid / 48, o = tid % 48;
    const int i = blockIdx.x * 8 + row;

    sx[row][o] = g_xf[(size_t)i * 48 + o];
    float g = 0.f;
    const int* nb = &g_nbr[i * KNN];
#pragma unroll
    for (int k = 0; k < KNN; k++) {
        const int j = nb[k];
        g += g_dinv[j] * g_xf[(size_t)j * 48 + o];
    }
    sg[row][o] = g;
    if (o == 0) sdin[row] = g_dinv[i];
    __syncthreads();

    float a0 = 0.f, a1 = 0.f;
#pragma unroll
    for (int c = 0; c < 48; c++) {
        a0 += sx[row][c] * W0s[c * 48 + o];
        a1 += sg[row][c] * W1s[c * 48 + o];
    }
    const float v = bs[o] + a0 - sdin[row] * a1;
    out[(size_t)i * 48 + o] = fmaxf(v, 0.f);
}

// ============ launch ============
extern "C" void kernel_launch(void* const* d_in, const int* in_sizes, int n_in,
                              void* d_out, int out_size) {
    const float* x  = (const float*)d_in[0];
    const float* W0 = (const float*)d_in[1];
    const float* W1 = (const float*)d_in[2];
    const float* b  = (const float*)d_in[3];
    float* out = (float*)d_out;

    transpose_kernel<<<256, 192>>>(x);
    pack_kernel<<<NNODE / 256, 256>>>();
    knn_mma_kernel<<<512, 128>>>();
    merge12_kernel<<<NNODE / 256, 256>>>();
    rescore_kernel<<<NNODE / 4, 128>>>();
    dinv_kernel<<<NNODE / 256, 256>>>();
    out_kernel<<<NNODE / 8, 384>>>(W0, W1, b, out);
}